// round 8
// baseline (speedup 1.0000x reference)
#include <cuda_runtime.h>
#include <cuda_fp16.h>
#include <cstdint>

#define HID 128
#define MAXN 50176
#define MAXE 1605632
#define SCAN_BLOCKS 64

__device__ __align__(16) __half  g_hh [(size_t)MAXN * HID];  // encoder out (fp16)
__device__ __align__(16) uint8_t g_h8 [(size_t)MAXN * HID];  // layer-0 feat int8 (0..127)
__device__ __align__(16) uint8_t g_hb8[(size_t)MAXN * HID];  // layer-1 feat int8 (0..127)
__device__ float g_sc [(size_t)MAXN * 8];  // layer-0 block scales (16 feats/block)
__device__ float g_sc2[(size_t)MAXN * 8];  // layer-1 block scales
__device__ float g_si [MAXN];
__device__ float g_sj [MAXN];
__device__ float g_si2[MAXN];
__device__ float g_sj2[MAXN];
__device__ int   g_deg[MAXN];   // INVARIANT: all-zero at kernel_launch entry
__device__ int   g_start[MAXN];
__device__ int   g_cursor[MAXN];
__device__ int   g_sorted[MAXE];
__device__ int   g_bsum[SCAN_BLOCKS];

// ---------------------------------------------------------------------------
// Inline edge-dtype detection (per warp): odd int32 words of int64 data
// (values < 50000, little-endian) are all zero.
// ---------------------------------------------------------------------------
__device__ __forceinline__ int detect_is64(const int* __restrict__ p) {
    int lane = threadIdx.x & 31;
    unsigned v = 0;
#pragma unroll
    for (int j = 0; j < 4; j++)
        v |= (unsigned)p[2 * (lane * 4 + j) + 1];
    unsigned any = __ballot_sync(0xFFFFFFFFu, v != 0);
    return any == 0;
}

// ---------------------------------------------------------------------------
// GEMM helpers (fp16 mma, fp32 accum)
// ---------------------------------------------------------------------------
__device__ __forceinline__ void ldsm_x4(unsigned* a, uint32_t addr) {
    asm volatile("ldmatrix.sync.aligned.m8n8.x4.shared.b16 {%0,%1,%2,%3}, [%4];"
                 : "=r"(a[0]), "=r"(a[1]), "=r"(a[2]), "=r"(a[3]) : "r"(addr));
}
__device__ __forceinline__ void ldsm_x2_trans(unsigned* b, uint32_t addr) {
    asm volatile("ldmatrix.sync.aligned.m8n8.x2.trans.shared.b16 {%0,%1}, [%2];"
                 : "=r"(b[0]), "=r"(b[1]) : "r"(addr));
}
__device__ __forceinline__ void mma16816(float* c, const unsigned* a, const unsigned* b) {
    asm volatile("mma.sync.aligned.m16n8k16.row.col.f32.f16.f16.f32 "
                 "{%0,%1,%2,%3}, {%4,%5,%6,%7}, {%8,%9}, {%0,%1,%2,%3};"
                 : "+f"(c[0]), "+f"(c[1]), "+f"(c[2]), "+f"(c[3])
                 : "r"(a[0]), "r"(a[1]), "r"(a[2]), "r"(a[3]),
                   "r"(b[0]), "r"(b[1]));
}

// ---------------------------------------------------------------------------
// Mega-kernel A: blocks [0,Ggemm) = encoder GEMM; the rest = dst histogram.
// ---------------------------------------------------------------------------
__global__ void __launch_bounds__(256) gemm_hist_kernel(
        const float* __restrict__ A, const float* __restrict__ W,
        const float* __restrict__ bias, const int* __restrict__ ei,
        int M, int E, int Ggemm) {
    const int LDA = 40;
    const int LDB = 136;
    __shared__ __half As[128 * LDA];
    __shared__ __half Bs[32 * LDB];

    if (blockIdx.x >= Ggemm) {
        int is64 = detect_is64(ei);
        int base = (blockIdx.x - Ggemm) * 2048 + threadIdx.x;
#pragma unroll
        for (int i = 0; i < 8; i++) {
            int e = base + i * 256;
            if (e < E) {
                int d = is64 ? ei[2 * (E + e)] : ei[E + e];
                atomicAdd(&g_deg[d], 1);
            }
        }
        return;
    }

    int tid = threadIdx.x;
    int warp = tid >> 5;
    int lane = tid & 31;
    int warp_m = warp >> 2;
    int warp_n = warp & 3;
    int bm = blockIdx.x * 128;

    uint32_t sA = (uint32_t)__cvta_generic_to_shared(As);
    uint32_t sB = (uint32_t)__cvta_generic_to_shared(Bs);

    float c[4][4][4];
#pragma unroll
    for (int mt = 0; mt < 4; mt++)
#pragma unroll
        for (int nt = 0; nt < 4; nt++)
#pragma unroll
            for (int r = 0; r < 4; r++) c[mt][nt][r] = 0.f;

    for (int k0 = 0; k0 < 256; k0 += 32) {
#pragma unroll
        for (int i = 0; i < 4; i++) {
            int t = tid + i * 256;
            int r = t >> 3;
            int c4 = t & 7;
            int row = bm + r;
            float4 v = make_float4(0.f, 0.f, 0.f, 0.f);
            if (row < M)
                v = *(const float4*)(A + (size_t)row * 256 + k0 + c4 * 4);
            __half2 h01 = __floats2half2_rn(v.x, v.y);
            __half2 h23 = __floats2half2_rn(v.z, v.w);
            uint2 u = make_uint2(*(unsigned*)&h01, *(unsigned*)&h23);
            *(uint2*)(As + r * LDA + c4 * 4) = u;
        }
#pragma unroll
        for (int i = 0; i < 4; i++) {
            int t = tid + i * 256;
            int r = t >> 5;
            int c4 = t & 31;
            float4 v = *(const float4*)(W + (size_t)(k0 + r) * 128 + c4 * 4);
            __half2 h01 = __floats2half2_rn(v.x, v.y);
            __half2 h23 = __floats2half2_rn(v.z, v.w);
            uint2 u = make_uint2(*(unsigned*)&h01, *(unsigned*)&h23);
            *(uint2*)(Bs + r * LDB + c4 * 4) = u;
        }
        __syncthreads();
#pragma unroll
        for (int ks = 0; ks < 2; ks++) {
            int ko = ks * 16;
            unsigned a[4][4], b[4][2];
#pragma unroll
            for (int mt = 0; mt < 4; mt++) {
                uint32_t addr = sA + 2u * (uint32_t)((warp_m * 64 + mt * 16 + (lane & 15)) * LDA
                                           + ko + (lane >> 4) * 8);
                ldsm_x4(a[mt], addr);
            }
#pragma unroll
            for (int nt = 0; nt < 4; nt++) {
                uint32_t addr = sB + 2u * (uint32_t)((ko + (lane & 15)) * LDB
                                           + warp_n * 32 + nt * 8);
                ldsm_x2_trans(b[nt], addr);
            }
#pragma unroll
            for (int mt = 0; mt < 4; mt++)
#pragma unroll
                for (int nt = 0; nt < 4; nt++)
                    mma16816(c[mt][nt], a[mt], b[nt]);
        }
        __syncthreads();
    }

#pragma unroll
    for (int nt = 0; nt < 4; nt++) {
        int col = warp_n * 32 + nt * 8 + (lane & 3) * 2;
        float b0 = __ldg(bias + col);
        float b1 = __ldg(bias + col + 1);
#pragma unroll
        for (int mt = 0; mt < 4; mt++) {
            int row = bm + warp_m * 64 + mt * 16 + (lane >> 2);
            if (row < M) {
                float v0 = c[mt][nt][0] + b0;
                float v1 = c[mt][nt][1] + b1;
                __half2 h = __floats2half2_rn(v0 > 0.f ? v0 : 0.f,
                                              v1 > 0.f ? v1 : 0.f);
                *(__half2*)(g_hh + (size_t)row * HID + col) = h;
            }
            if (row + 8 < M) {
                float v0 = c[mt][nt][2] + b0;
                float v1 = c[mt][nt][3] + b1;
                __half2 h = __floats2half2_rn(v0 > 0.f ? v0 : 0.f,
                                              v1 > 0.f ? v1 : 0.f);
                *(__half2*)(g_hh + (size_t)(row + 8) * HID + col) = h;
            }
        }
    }
}

// ---------------------------------------------------------------------------
// CSR scan stages
// ---------------------------------------------------------------------------
__global__ void scan_block_kernel(int n) {
    __shared__ int warp_tot[32];
    int tid = threadIdx.x;
    int lane = tid & 31;
    int wid = tid >> 5;
    int i = blockIdx.x * 1024 + tid;
    int v = (i < n) ? g_deg[i] : 0;
    int x = v;
#pragma unroll
    for (int o = 1; o < 32; o <<= 1) {
        int y = __shfl_up_sync(0xFFFFFFFFu, x, o);
        if (lane >= o) x += y;
    }
    if (lane == 31) warp_tot[wid] = x;
    __syncthreads();
    if (wid == 0) {
        int t = warp_tot[lane];
#pragma unroll
        for (int o = 1; o < 32; o <<= 1) {
            int y = __shfl_up_sync(0xFFFFFFFFu, t, o);
            if (lane >= o) t += y;
        }
        warp_tot[lane] = t;
    }
    __syncthreads();
    int off = wid ? warp_tot[wid - 1] : 0;
    int incl = x + off;
    if (i < n) g_start[i] = incl - v;
    if (tid == 1023) g_bsum[blockIdx.x] = incl;
}

__global__ void add_off_kernel(int n, int nb) {
    __shared__ int boff_s;
    int tid = threadIdx.x;
    int b = blockIdx.x;
    if (tid < 32) {
        int acc = 0;
#pragma unroll
        for (int j = 0; j < 2; j++) {
            int idx = tid + j * 32;
            if (idx < b && idx < nb) acc += g_bsum[idx];
        }
#pragma unroll
        for (int o = 16; o; o >>= 1)
            acc += __shfl_xor_sync(0xFFFFFFFFu, acc, o);
        if (tid == 0) boff_s = acc;
    }
    __syncthreads();
    int i = b * 1024 + tid;
    if (i < n) {
        int s = g_start[i] + boff_s;
        g_start[i] = s;
        g_cursor[i] = s;
    }
}

// ---------------------------------------------------------------------------
// Mega-kernel B: blocks [0,Gs) = CSR scatter; rest = layer-1 dots + int8
// quantization of g_hh into g_h8/g_sc (warp per node).
// ---------------------------------------------------------------------------
__global__ void __launch_bounds__(256) scatter_dots_kernel(
        const int* __restrict__ ei, const float* __restrict__ w,
        int E, int n, int Gs) {
    if (blockIdx.x < Gs) {
        int is64 = detect_is64(ei);
        int base = blockIdx.x * 2048 + threadIdx.x;
#pragma unroll
        for (int i = 0; i < 8; i++) {
            int e = base + i * 256;
            if (e < E) {
                int s, d;
                if (is64) { s = ei[2 * e]; d = ei[2 * (E + e)]; }
                else      { s = ei[e];     d = ei[E + e]; }
                int pos = atomicAdd(&g_cursor[d], 1);
                g_sorted[pos] = s;
            }
        }
        return;
    }
    int node = (blockIdx.x - Gs) * 8 + (threadIdx.x >> 5);
    int lane = threadIdx.x & 31;
    if (node >= n) return;
    uint2 raw = *((const uint2*)(g_hh + (size_t)node * HID) + lane);
    float2 f01 = __half22float2(*(__half2*)&raw.x);
    float2 f23 = __half22float2(*(__half2*)&raw.y);
    float4 wi = ((const float4*)w)[lane];
    float4 wj = ((const float4*)w)[32 + lane];
    float si = f01.x * wi.x + f01.y * wi.y + f23.x * wi.z + f23.y * wi.w;
    float sj = f01.x * wj.x + f01.y * wj.y + f23.x * wj.z + f23.y * wj.w;
#pragma unroll
    for (int o = 16; o; o >>= 1) {
        si += __shfl_xor_sync(0xFFFFFFFFu, si, o);
        sj += __shfl_xor_sync(0xFFFFFFFFu, sj, o);
    }
    if (lane == 0) { g_si[node] = si; g_sj[node] = sj; }
    // Quantize: 4 features per lane; block = 16 feats = 4 lanes (lane>>2).
    float m = fmaxf(fmaxf(f01.x, f01.y), fmaxf(f23.x, f23.y));
    m = fmaxf(m, __shfl_xor_sync(0xFFFFFFFFu, m, 1));
    m = fmaxf(m, __shfl_xor_sync(0xFFFFFFFFu, m, 2));
    float invq = m > 0.f ? 127.f / m : 0.f;
    unsigned q0 = (unsigned)__float2int_rn(f01.x * invq);
    unsigned q1 = (unsigned)__float2int_rn(f01.y * invq);
    unsigned q2 = (unsigned)__float2int_rn(f23.x * invq);
    unsigned q3 = (unsigned)__float2int_rn(f23.y * invq);
    unsigned packed = q0 | (q1 << 8) | (q2 << 16) | (q3 << 24);
    ((unsigned*)(g_h8 + (size_t)node * HID))[lane] = packed;
    if ((lane & 3) == 0) g_sc[(size_t)node * 8 + (lane >> 2)] = m * (1.f / 127.f);
}

// ---------------------------------------------------------------------------
// int8 gather-accumulate: 4 edges per warp step (8 lanes/edge, uint4 = 16
// int8 features/lane). grp = lane>>3 selects the edge, sub = lane&7 the
// 16-feature block. After xor(8)+xor(16) ALL lanes hold full sums for
// features [sub*16, sub*16+16).
// ---------------------------------------------------------------------------
__device__ __forceinline__ void agg_accum_i8(
        const uint8_t* __restrict__ featq, const float* __restrict__ sctab,
        const float* __restrict__ sjtab, int k0, int deg, float sib,
        int grp, int sub, float* acc) {
#pragma unroll
    for (int r = 0; r < 16; r++) acc[r] = 0.f;
    int kend = k0 + deg;
#pragma unroll 2
    for (int k = k0 + grp; k < kend; k += 4) {
        int s = g_sorted[k];
        float z = sib + sjtab[s];
        float alpha = 1.0f / (1.0f + __expf(-z));
        float beta = alpha * sctab[(size_t)s * 8 + sub];
        uint4 q = *((const uint4*)(featq + (size_t)s * HID) + sub);
        unsigned wq;
        wq = q.x;
        acc[0]  += beta * (float)(wq & 0xFF);
        acc[1]  += beta * (float)((wq >> 8) & 0xFF);
        acc[2]  += beta * (float)((wq >> 16) & 0xFF);
        acc[3]  += beta * (float)(wq >> 24);
        wq = q.y;
        acc[4]  += beta * (float)(wq & 0xFF);
        acc[5]  += beta * (float)((wq >> 8) & 0xFF);
        acc[6]  += beta * (float)((wq >> 16) & 0xFF);
        acc[7]  += beta * (float)(wq >> 24);
        wq = q.z;
        acc[8]  += beta * (float)(wq & 0xFF);
        acc[9]  += beta * (float)((wq >> 8) & 0xFF);
        acc[10] += beta * (float)((wq >> 16) & 0xFF);
        acc[11] += beta * (float)(wq >> 24);
        wq = q.w;
        acc[12] += beta * (float)(wq & 0xFF);
        acc[13] += beta * (float)((wq >> 8) & 0xFF);
        acc[14] += beta * (float)((wq >> 16) & 0xFF);
        acc[15] += beta * (float)(wq >> 24);
    }
#pragma unroll
    for (int r = 0; r < 16; r++) {
        acc[r] += __shfl_xor_sync(0xFFFFFFFFu, acc[r], 8);
        acc[r] += __shfl_xor_sync(0xFFFFFFFFu, acc[r], 16);
    }
}

// ---------------------------------------------------------------------------
// Layer 1: hb = relu(acc/max(deg,1)); fused layer-2 dots; int8 quantize out.
// ---------------------------------------------------------------------------
__global__ void agg1_kernel(const float* __restrict__ bptr,
                            const float* __restrict__ att2w, int n) {
    int d = (blockIdx.x * blockDim.x + threadIdx.x) >> 5;
    int lane = threadIdx.x & 31;
    if (d >= n) return;
    int grp = lane >> 3, sub = lane & 7;
    float acc[16];
    float sib = g_si[d] + bptr[0];
    agg_accum_i8(g_h8, g_sc, g_sj, g_start[d], g_deg[d], sib, grp, sub, acc);
    int deg = g_deg[d];
    float inv = 1.0f / (float)(deg < 1 ? 1 : deg);
    float f[16], bmax = 0.f;
#pragma unroll
    for (int r = 0; r < 16; r++) {
        f[r] = fmaxf(acc[r] * inv, 0.f);
        bmax = fmaxf(bmax, f[r]);
    }
    // fused layer-2 dots (features [sub*16, +16))
    const float* wi = att2w + sub * 16;
    const float* wj = att2w + 128 + sub * 16;
    float si = 0.f, sj = 0.f;
#pragma unroll
    for (int r = 0; r < 16; r++) {
        si += f[r] * __ldg(wi + r);
        sj += f[r] * __ldg(wj + r);
    }
#pragma unroll
    for (int o = 4; o; o >>= 1) {
        si += __shfl_xor_sync(0xFFFFFFFFu, si, o);
        sj += __shfl_xor_sync(0xFFFFFFFFu, sj, o);
    }
    if (lane == 0) { g_si2[d] = si; g_sj2[d] = sj; }
    // int8 quantize (block = this lane's 16 features)
    float invq = bmax > 0.f ? 127.f / bmax : 0.f;
    if (grp == 0) {
        unsigned u[4];
#pragma unroll
        for (int g = 0; g < 4; g++) {
            unsigned b0 = (unsigned)__float2int_rn(f[g * 4 + 0] * invq);
            unsigned b1 = (unsigned)__float2int_rn(f[g * 4 + 1] * invq);
            unsigned b2 = (unsigned)__float2int_rn(f[g * 4 + 2] * invq);
            unsigned b3 = (unsigned)__float2int_rn(f[g * 4 + 3] * invq);
            u[g] = b0 | (b1 << 8) | (b2 << 16) | (b3 << 24);
        }
        uint4 packed = make_uint4(u[0], u[1], u[2], u[3]);
        *((uint4*)(g_hb8 + (size_t)d * HID) + sub) = packed;
        g_sc2[(size_t)d * 8 + sub] = bmax * (1.f / 127.f);
    }
}

// ---------------------------------------------------------------------------
// Layer 2 + classifier; restores g_deg invariant.
// ---------------------------------------------------------------------------
__global__ void agg2_cls_kernel(const float* __restrict__ bptr,
                                const float* __restrict__ clsw,
                                const float* __restrict__ clsb,
                                float* __restrict__ out, int n) {
    int d = (blockIdx.x * blockDim.x + threadIdx.x) >> 5;
    int lane = threadIdx.x & 31;
    if (d >= n) return;
    int grp = lane >> 3, sub = lane & 7;
    float acc[16];
    float sib = g_si2[d] + bptr[0];
    agg_accum_i8(g_hb8, g_sc2, g_sj2, g_start[d], g_deg[d], sib, grp, sub, acc);
    int deg = g_deg[d];
    if (lane == 0) g_deg[d] = 0;   // restore invariant for next replay
    float inv = 1.0f / (float)(deg < 1 ? 1 : deg);
    float o0 = 0.f, o1 = 0.f;
#pragma unroll
    for (int r = 0; r < 16; r++) {
        float v = acc[r] * inv;
        int j = sub * 16 + r;
        o0 += v * __ldg(clsw + j * 2);
        o1 += v * __ldg(clsw + j * 2 + 1);
    }
#pragma unroll
    for (int o = 4; o; o >>= 1) {
        o0 += __shfl_xor_sync(0xFFFFFFFFu, o0, o);
        o1 += __shfl_xor_sync(0xFFFFFFFFu, o1, o);
    }
    if (lane == 0) {
        out[(size_t)d * 2 + 0] = o0 + clsb[0];
        out[(size_t)d * 2 + 1] = o1 + clsb[1];
    }
}

// ---------------------------------------------------------------------------
extern "C" void kernel_launch(void* const* d_in, const int* in_sizes, int n_in,
                              void* d_out, int out_size) {
    const float* x      = (const float*)d_in[0];
    const int*   ei     = (const int*)  d_in[1];
    const float* enc_w  = (const float*)d_in[2];
    const float* enc_b  = (const float*)d_in[3];
    const float* att1_w = (const float*)d_in[4];
    const float* att1_b = (const float*)d_in[5];
    const float* att2_w = (const float*)d_in[6];
    const float* att2_b = (const float*)d_in[7];
    const float* cls_w  = (const float*)d_in[8];
    const float* cls_b  = (const float*)d_in[9];
    float* out = (float*)d_out;

    int N = in_sizes[0] / 256;
    int E = in_sizes[1] / 2;
    int nb = (N + 1023) / 1024;
    int Ggemm = (N + 127) / 128;
    int Gh = (E + 2047) / 2048;
    int Gd = (N + 7) / 8;

    // A: encoder GEMM (tensor cores) overlapped with dst histogram
    gemm_hist_kernel<<<Ggemm + Gh, 256>>>(x, enc_w, enc_b, ei, N, E, Ggemm);
    // CSR offsets
    scan_block_kernel<<<nb, 1024>>>(N);
    add_off_kernel<<<nb, 1024>>>(N, nb);
    // B: CSR scatter overlapped with layer-1 dots + int8 quantization
    scatter_dots_kernel<<<Gh + Gd, 256>>>(ei, att1_w, E, N, Gh);
    // Layer 1 (int8 gather, fused layer-2 dots, int8 requantize)
    agg1_kernel<<<Gd, 256>>>(att1_b, att2_w, N);
    // Layer 2 + classifier (+ deg invariant restore)
    agg2_cls_kernel<<<Gd, 256>>>(att2_b, cls_w, cls_b, out, N);
}